// round 2
// baseline (speedup 1.0000x reference)
#include <cuda_runtime.h>
#include <cuda_bf16.h>

// out[row,m] = ( fp32FWHT_m( sum_d fma-chain x[row,d]*W[m,d] ) * (1/sqrt(128)) > 0 ) ? 1 : 0
//
// Bit-match strategy vs the (CPU/Eigen fp32) reference:
//  - GEMM: ONE fp32 accumulator per output, strictly sequential fmaf over d=0..1023
//    (matches Eigen gebp's per-output fma chain).
//  - FWHT: identical butterfly pairing/order as the reference, fp32 a+b / a-b,
//    then multiply by the fp32-rounded 1/sqrt(128), then >0.
//
// x [32768,1024] fp32, W [128,1024] fp32, out [32768,128] fp32.

#define MOUT 128
#define BM   128
#define BK   16

__global__ void __launch_bounds__(256, 2)
gemm_fwht_sign_kernel(const float* __restrict__ x, const float* __restrict__ W,
                      float* __restrict__ out, int K) {
    // smem: GEMM tiles overlaid with the FWHT row buffer (used after GEMM done)
    __shared__ __align__(16) char smbuf[64 * (MOUT + 4) * 4];   // 33792 B >= 16384 B
    float (*As)[BM]       = reinterpret_cast<float(*)[BM]>(smbuf);
    float (*Bs)[MOUT]     = reinterpret_cast<float(*)[MOUT]>(smbuf + BK * BM * 4);
    float (*hb)[MOUT + 4] = reinterpret_cast<float(*)[MOUT + 4]>(smbuf);

    const int tid = threadIdx.x;      // 0..255
    const int tr  = tid >> 4;         // 0..15
    const int tc  = tid & 15;         // 0..15
    const int block_row = blockIdx.x * BM;

    const int r0 = tid >> 2;          // 0..63
    const int q0 = tid & 3;

    const float4* xA0 = (const float4*)(x + (size_t)(block_row + r0) * K) + q0;
    const float4* xA1 = (const float4*)(x + (size_t)(block_row + r0 + 64) * K) + q0;
    const float4* wB0 = (const float4*)(W + (size_t)r0 * K) + q0;
    const float4* wB1 = (const float4*)(W + (size_t)(r0 + 64) * K) + q0;

    float acc[8][8];
#pragma unroll
    for (int i = 0; i < 8; ++i)
#pragma unroll
        for (int j = 0; j < 8; ++j) acc[i][j] = 0.0f;

    const int nkt = K / BK;           // 64

    float4 pa0 = xA0[0];
    float4 pa1 = xA1[0];
    float4 pb0 = wB0[0];
    float4 pb1 = wB1[0];

    for (int kt = 0; kt < nkt; ++kt) {
        const int kc = q0 * 4;
        As[kc + 0][r0] = pa0.x; As[kc + 1][r0] = pa0.y;
        As[kc + 2][r0] = pa0.z; As[kc + 3][r0] = pa0.w;
        As[kc + 0][r0 + 64] = pa1.x; As[kc + 1][r0 + 64] = pa1.y;
        As[kc + 2][r0 + 64] = pa1.z; As[kc + 3][r0 + 64] = pa1.w;
        Bs[kc + 0][r0] = pb0.x; Bs[kc + 1][r0] = pb0.y;
        Bs[kc + 2][r0] = pb0.z; Bs[kc + 3][r0] = pb0.w;
        Bs[kc + 0][r0 + 64] = pb1.x; Bs[kc + 1][r0 + 64] = pb1.y;
        Bs[kc + 2][r0 + 64] = pb1.z; Bs[kc + 3][r0 + 64] = pb1.w;
        __syncthreads();

        if (kt + 1 < nkt) {
            const int off = (kt + 1) * (BK / 4);
            pa0 = xA0[off]; pa1 = xA1[off];
            pb0 = wB0[off]; pb1 = wB1[off];
        }

        // strictly sequential k accumulation: d ascending within tile, tiles ascending
#pragma unroll
        for (int k = 0; k < BK; ++k) {
            float4 a0 = *(const float4*)&As[k][tr * 8];
            float4 a1 = *(const float4*)&As[k][tr * 8 + 4];
            float4 b0 = *(const float4*)&Bs[k][tc * 8];
            float4 b1 = *(const float4*)&Bs[k][tc * 8 + 4];
            float av[8] = {a0.x, a0.y, a0.z, a0.w, a1.x, a1.y, a1.z, a1.w};
            float bv[8] = {b0.x, b0.y, b0.z, b0.w, b1.x, b1.y, b1.z, b1.w};
#pragma unroll
            for (int i = 0; i < 8; ++i)
#pragma unroll
                for (int j = 0; j < 8; ++j)
                    acc[i][j] = fmaf(av[i], bv[j], acc[i][j]);
        }
        __syncthreads();
    }

    // ---- epilogue: fp32 FWHT along m (reference butterfly order) + sign ----
    const float scale = 0.08838834764831844f;   // fp32( 1/sqrt(128) )

    for (int hs = 0; hs < 2; ++hs) {            // rows [0,64) then [64,128)
        __syncthreads();
        if ((tr >> 3) == hs) {
            const int rbase = (tr & 7) * 8;
#pragma unroll
            for (int i = 0; i < 8; ++i)
#pragma unroll
                for (int j = 0; j < 8; ++j)
                    hb[rbase + i][tc * 8 + j] = acc[i][j];
        }
        __syncthreads();

        for (int half = 1; half < MOUT; half <<= 1) {
#pragma unroll
            for (int p = 0; p < 16; ++p) {      // 4096 pairs / 256 threads
                const int pidx = tid + p * 256;
                const int row = pidx >> 6;
                const int t   = pidx & 63;
                const int j   = ((t & ~(half - 1)) << 1) | (t & (half - 1));
                const float a = hb[row][j];
                const float b = hb[row][j + half];
                hb[row][j]        = a + b;
                hb[row][j + half] = a - b;
            }
            __syncthreads();
        }

#pragma unroll
        for (int p = 0; p < 8; ++p) {           // 2048 float4 stores
            const int f4  = tid + p * 256;
            const int row = f4 >> 5;
            const int c   = (f4 & 31) * 4;
            float4 v = *(const float4*)&hb[row][c];
            float4 o;
            o.x = (v.x * scale > 0.0f) ? 1.0f : 0.0f;
            o.y = (v.y * scale > 0.0f) ? 1.0f : 0.0f;
            o.z = (v.z * scale > 0.0f) ? 1.0f : 0.0f;
            o.w = (v.w * scale > 0.0f) ? 1.0f : 0.0f;
            *(float4*)(out + (size_t)(block_row + hs * 64 + row) * MOUT + c) = o;
        }
    }
}

extern "C" void kernel_launch(void* const* d_in, const int* in_sizes, int n_in,
                              void* d_out, int out_size) {
    const float* x = (const float*)d_in[0];   // [rows, K]
    const float* W = (const float*)d_in[1];   // [128, K]
    float* out = (float*)d_out;               // [rows, 128]

    const int K = in_sizes[1] / MOUT;         // 1024
    const int rows = in_sizes[0] / K;         // 32768

    gemm_fwht_sign_kernel<<<rows / BM, 256>>>(x, W, out, K);
}